// round 3
// baseline (speedup 1.0000x reference)
#include <cuda_runtime.h>
#include <cuda_bf16.h>
#include <math.h>

// Problem constants
constexpr int Bb = 4, Nn = 325, Tt = 48, Dd = 128, Hh = 8;
constexpr int M  = Bb * Nn * Tt;      // 62400 tokens
constexpr float SCALE = 0.25f;        // HD^-0.5, HD=16
constexpr float EPS = 1e-5f;

// Scratch buffers (static device globals — no runtime allocation)
__device__ float g_h  [M * 128];
__device__ float g_qkv[M * 384];
__device__ float g_att[M * 128];
__device__ float g_x1 [M * 128];
__device__ float g_x2 [M * 128];
__device__ float g_ffh[M * 512];

// ---------------------------------------------------------------------------
// LayerNorm: one warp per token row of 128 floats
// ---------------------------------------------------------------------------
__global__ void ln_kernel(const float* __restrict__ X,
                          const float* __restrict__ s,
                          const float* __restrict__ b,
                          float* __restrict__ O, int rows)
{
    int gw   = (blockIdx.x * blockDim.x + threadIdx.x) >> 5;
    int lane = threadIdx.x & 31;
    if (gw >= rows) return;
    float4 v = ((const float4*)(X + (size_t)gw * 128))[lane];
    float sum = v.x + v.y + v.z + v.w;
    #pragma unroll
    for (int o = 16; o; o >>= 1) sum += __shfl_xor_sync(0xffffffffu, sum, o);
    float mean = sum * (1.0f / 128.0f);
    float dx = (v.x - mean) * (v.x - mean) + (v.y - mean) * (v.y - mean)
             + (v.z - mean) * (v.z - mean) + (v.w - mean) * (v.w - mean);
    #pragma unroll
    for (int o = 16; o; o >>= 1) dx += __shfl_xor_sync(0xffffffffu, dx, o);
    float rstd = rsqrtf(dx * (1.0f / 128.0f) + EPS);
    float4 sv = ((const float4*)s)[lane];
    float4 bv = ((const float4*)b)[lane];
    float4 o4;
    o4.x = (v.x - mean) * rstd * sv.x + bv.x;
    o4.y = (v.y - mean) * rstd * sv.y + bv.y;
    o4.z = (v.z - mean) * rstd * sv.z + bv.z;
    o4.w = (v.w - mean) * rstd * sv.w + bv.w;
    ((float4*)(O + (size_t)gw * 128))[lane] = o4;
}

// ---------------------------------------------------------------------------
// Tiled SGEMM: C[M,N] = A[M,K] @ B[K,N] + bias (+res) (gelu)
// BM=BN=64, BK=32, 256 threads, 4x4 micro-tile per thread.
// EPI: 0 = bias, 1 = bias + residual, 2 = bias + exact GELU
// ---------------------------------------------------------------------------
constexpr int BM = 64, BN = 64, BK = 32;

template <int EPI>
__global__ __launch_bounds__(256)
void gemm_kernel(const float* __restrict__ A, const float* __restrict__ Bw,
                 const float* __restrict__ bias, const float* __restrict__ Res,
                 float* __restrict__ C, int Mm, int Nc, int K)
{
    __shared__ float As[BK][BM];
    __shared__ float Bs[BK][BN];
    const int tid = threadIdx.x;
    const int m0 = blockIdx.y * BM;
    const int n0 = blockIdx.x * BN;
    const int tx = tid & 15, ty = tid >> 4;

    float acc[4][4] = {};

    for (int k0 = 0; k0 < K; k0 += BK) {
        #pragma unroll
        for (int u = 0; u < 2; u++) {          // A tile: 64x32, transposed store
            int f = tid + u * 256;             // 512 float4
            int row = f >> 3;
            int c4  = f & 7;
            float4 v = *(const float4*)(A + (size_t)(m0 + row) * K + k0 + c4 * 4);
            As[c4 * 4 + 0][row] = v.x;
            As[c4 * 4 + 1][row] = v.y;
            As[c4 * 4 + 2][row] = v.z;
            As[c4 * 4 + 3][row] = v.w;
        }
        #pragma unroll
        for (int u = 0; u < 2; u++) {          // B tile: 32x64
            int f = tid + u * 256;
            int row = f >> 4;
            int c4  = f & 15;
            *(float4*)(&Bs[row][c4 * 4]) =
                *(const float4*)(Bw + (size_t)(k0 + row) * Nc + n0 + c4 * 4);
        }
        __syncthreads();
        #pragma unroll
        for (int kk = 0; kk < BK; kk++) {
            float4 a = *(const float4*)(&As[kk][ty * 4]);
            float4 b = *(const float4*)(&Bs[kk][tx * 4]);
            float av[4] = {a.x, a.y, a.z, a.w};
            float bv[4] = {b.x, b.y, b.z, b.w};
            #pragma unroll
            for (int i = 0; i < 4; i++)
                #pragma unroll
                for (int j = 0; j < 4; j++)
                    acc[i][j] += av[i] * bv[j];
        }
        __syncthreads();
    }

    #pragma unroll
    for (int i = 0; i < 4; i++) {
        int m = m0 + ty * 4 + i;
        #pragma unroll
        for (int j = 0; j < 4; j++) {
            int n = n0 + tx * 4 + j;
            float v = acc[i][j] + bias[n];
            if (EPI == 1) v += Res[(size_t)m * Nc + n];
            if (EPI == 2) v = 0.5f * v * (1.0f + erff(v * 0.70710678118654752f));
            C[(size_t)m * Nc + n] = v;
        }
    }
}

// ---------------------------------------------------------------------------
// Temporal attention: block per (b,n,head), L=48, HD=16, full scores in smem
// qkv layout per token: [3][H][16] -> q at +0, k at +128, v at +256 (+h*16)
// ---------------------------------------------------------------------------
__global__ __launch_bounds__(64)
void attn_temporal(const float* __restrict__ qkv, float* __restrict__ att)
{
    int h  = blockIdx.x & 7;
    int bn = blockIdx.x >> 3;
    __shared__ float q[48][16], k[48][16], v[48][16];
    __shared__ float sc[48][48];
    int tid = threadIdx.x;

    size_t base = (size_t)bn * 48 * 384 + h * 16;
    for (int i = tid; i < 48 * 4; i += 64) {
        int row = i >> 2, seg = i & 3;
        const float* p = qkv + base + (size_t)row * 384;
        ((float4*)q[row])[seg] = ((const float4*)(p))[seg];
        ((float4*)k[row])[seg] = ((const float4*)(p + 128))[seg];
        ((float4*)v[row])[seg] = ((const float4*)(p + 256))[seg];
    }
    __syncthreads();

    for (int i = tid; i < 48 * 48; i += 64) {
        int qi = i / 48, ki = i % 48;
        float s = 0.f;
        #pragma unroll
        for (int d = 0; d < 16; d++) s += q[qi][d] * k[ki][d];
        sc[qi][ki] = s * SCALE;
    }
    __syncthreads();

    if (tid < 48) {
        float mx = -3.4e38f;
        for (int j = 0; j < 48; j++) mx = fmaxf(mx, sc[tid][j]);
        float l = 0.f;
        for (int j = 0; j < 48; j++) {
            float p = __expf(sc[tid][j] - mx);
            sc[tid][j] = p; l += p;
        }
        float inv = 1.0f / l;
        for (int j = 0; j < 48; j++) sc[tid][j] *= inv;
    }
    __syncthreads();

    for (int i = tid; i < 48 * 16; i += 64) {
        int qi = i >> 4, d = i & 15;
        float o = 0.f;
        for (int kk = 0; kk < 48; kk++) o += sc[qi][kk] * v[kk][d];
        att[(size_t)(bn * 48 + qi) * 128 + h * 16 + d] = o;
    }
}

// ---------------------------------------------------------------------------
// Spatial attention (flash-style): block per (b,t,head), L=325 over n
// Thread = one query row; keys streamed in 32-row smem tiles; online softmax.
// Token index for (b,n,t) = (b*Nn+n)*Tt + t  (no physical transpose needed).
// NOTE: mask is read as int32 (harness materializes JAX bool as int32;
// int reads are also in-bounds/correct if it were uint8 with all-ones).
// ---------------------------------------------------------------------------
constexpr int KT = 32;

__global__ __launch_bounds__(352)
void attn_spatial(const float* __restrict__ qkv, const int* __restrict__ mask,
                  float* __restrict__ att)
{
    int h  = blockIdx.x & 7;
    int bt = blockIdx.x >> 3;
    int t  = bt % Tt, b = bt / Tt;
    int tid = threadIdx.x;
    int nq  = tid;
    bool active = nq < Nn;

    __shared__ float ks[KT][16], vs[KT][16];
    __shared__ int   msk[KT];

    float qr[16];
    float acc[16] = {};
    float m = -3.4e38f, l = 0.f;

    if (active) {
        const float* p = qkv + ((size_t)(b * Nn + nq) * Tt + t) * 384 + h * 16;
        #pragma unroll
        for (int i = 0; i < 4; i++) ((float4*)qr)[i] = ((const float4*)p)[i];
    }

    for (int kt = 0; kt < Nn; kt += KT) {
        int nk = min(KT, Nn - kt);
        __syncthreads();
        if (tid < 128) {
            int r = tid >> 2, seg = tid & 3;
            if (r < nk) {
                const float* p = qkv + ((size_t)(b * Nn + kt + r) * Tt + t) * 384 + 128 + h * 16;
                ((float4*)ks[r])[seg] = ((const float4*)p)[seg];
            }
        } else if (tid < 256) {
            int r = (tid - 128) >> 2, seg = tid & 3;
            if (r < nk) {
                const float* p = qkv + ((size_t)(b * Nn + kt + r) * Tt + t) * 384 + 256 + h * 16;
                ((float4*)vs[r])[seg] = ((const float4*)p)[seg];
            }
        } else if (tid < 256 + KT) {
            int j = tid - 256;
            msk[j] = (kt + j < Nn) ? (mask[b * Nn + kt + j] != 0 ? 1 : 0) : 0;
        }
        __syncthreads();

        if (active) {
            float sarr[KT];
            #pragma unroll
            for (int j = 0; j < KT; j++) {
                float d = 0.f;
                #pragma unroll
                for (int dd = 0; dd < 16; dd++) d += qr[dd] * ks[j][dd];
                sarr[j] = msk[j] ? d * SCALE : -3.4e38f;
            }
            float tm = -3.4e38f;
            #pragma unroll
            for (int j = 0; j < KT; j++) tm = fmaxf(tm, sarr[j]);
            float mnew = fmaxf(m, tm);
            float corr = __expf(m - mnew);
            l *= corr;
            #pragma unroll
            for (int dd = 0; dd < 16; dd++) acc[dd] *= corr;
            #pragma unroll
            for (int j = 0; j < KT; j++) {
                float p = (sarr[j] > -3.0e38f) ? __expf(sarr[j] - mnew) : 0.f;
                l += p;
                #pragma unroll
                for (int dd = 0; dd < 16; dd++) acc[dd] += p * vs[j][dd];
            }
            m = mnew;
        }
    }

    if (active) {
        float inv = 1.0f / l;
        float* o = att + ((size_t)(b * Nn + nq) * Tt + t) * 128 + h * 16;
        #pragma unroll
        for (int dd = 0; dd < 16; dd++) o[dd] = acc[dd] * inv;
    }
}

// ---------------------------------------------------------------------------
// Orchestration
// ---------------------------------------------------------------------------
extern "C" void kernel_launch(void* const* d_in, const int* in_sizes, int n_in,
                              void* d_out, int out_size)
{
    const float* x       = (const float*)d_in[0];
    const int*   mask    = (const int*)  d_in[1];
    const float* ln1_s   = (const float*)d_in[2];
    const float* ln1_b   = (const float*)d_in[3];
    const float* tqkv_w  = (const float*)d_in[4];
    const float* tqkv_b  = (const float*)d_in[5];
    const float* tproj_w = (const float*)d_in[6];
    const float* tproj_b = (const float*)d_in[7];
    const float* ln2_s   = (const float*)d_in[8];
    const float* ln2_b   = (const float*)d_in[9];
    const float* sqkv_w  = (const float*)d_in[10];
    const float* sqkv_b  = (const float*)d_in[11];
    const float* sproj_w = (const float*)d_in[12];
    const float* sproj_b = (const float*)d_in[13];
    const float* ln3_s   = (const float*)d_in[14];
    const float* ln3_b   = (const float*)d_in[15];
    const float* fw1     = (const float*)d_in[16];
    const float* fb1     = (const float*)d_in[17];
    const float* fw2     = (const float*)d_in[18];
    const float* fb2     = (const float*)d_in[19];
    float* out = (float*)d_out;

    float *h, *qkv, *att, *x1, *x2, *ffh;
    cudaGetSymbolAddress((void**)&h,   g_h);
    cudaGetSymbolAddress((void**)&qkv, g_qkv);
    cudaGetSymbolAddress((void**)&att, g_att);
    cudaGetSymbolAddress((void**)&x1,  g_x1);
    cudaGetSymbolAddress((void**)&x2,  g_x2);
    cudaGetSymbolAddress((void**)&ffh, g_ffh);

    const int ln_grid = (M + 7) / 8;           // 8 warps (256 thr) per block
    dim3 g_qkv_grid(384 / BN, M / BM);
    dim3 g_d_grid  (128 / BN, M / BM);
    dim3 g_ffn1    (512 / BN, M / BM);

    // ---- temporal branch ----
    ln_kernel<<<ln_grid, 256>>>(x, ln1_s, ln1_b, h, M);
    gemm_kernel<0><<<g_qkv_grid, 256>>>(h, tqkv_w, tqkv_b, nullptr, qkv, M, 384, 128);
    attn_temporal<<<Bb * Nn * Hh, 64>>>(qkv, att);
    gemm_kernel<1><<<g_d_grid, 256>>>(att, tproj_w, tproj_b, x, x1, M, 128, 128);

    // ---- spatial branch ----
    ln_kernel<<<ln_grid, 256>>>(x1, ln2_s, ln2_b, h, M);
    gemm_kernel<0><<<g_qkv_grid, 256>>>(h, sqkv_w, sqkv_b, nullptr, qkv, M, 384, 128);
    attn_spatial<<<Bb * Tt * Hh, 352>>>(qkv, mask, att);
    gemm_kernel<1><<<g_d_grid, 256>>>(att, sproj_w, sproj_b, x1, x2, M, 128, 128);

    // ---- FFN ----
    ln_kernel<<<ln_grid, 256>>>(x2, ln3_s, ln3_b, h, M);
    gemm_kernel<2><<<g_ffn1, 256>>>(h, fw1, fb1, nullptr, ffh, M, 512, 128);
    gemm_kernel<1><<<g_d_grid, 256>>>(ffh, fw2, fb2, x2, out, M, 128, 512);
}

// round 5
// speedup vs baseline: 1.4011x; 1.4011x over previous
#include <cuda_runtime.h>
#include <cuda_bf16.h>
#include <math.h>
#include <stdint.h>

// Problem constants
constexpr int Bb = 4, Nn = 325, Tt = 48, Hh = 8;
constexpr int M  = Bb * Nn * Tt;      // 62400 tokens
constexpr int MT = 488;               // M tiles of 128
constexpr int M_PAD = MT * 128;       // 62464
constexpr float SCALE = 0.25f;        // HD^-0.5, HD=16
constexpr float EPS = 1e-5f;

// Scratch buffers (static device globals — zero-initialized; pad rows [M,M_PAD)
// are never written, so GEMM A-reads of pad rows see zeros).
__device__ float g_h  [M_PAD * 128];
__device__ float g_qkv[M_PAD * 384];
__device__ float g_att[M_PAD * 128];
__device__ float g_x1 [M_PAD * 128];
__device__ float g_x2 [M_PAD * 128];
__device__ float g_ffh[M_PAD * 512];

// ---------------------------------------------------------------------------
// Helpers: baseline-PTX tensor path (mma.sync + ldmatrix, sm_80-class)
// ---------------------------------------------------------------------------
__device__ __forceinline__ uint32_t s2u(const void* p) {
    uint32_t a;
    asm("{ .reg .u64 t; cvta.to.shared.u64 t, %1; cvt.u32.u64 %0, t; }"
        : "=r"(a) : "l"(p));
    return a;
}

__device__ __forceinline__ void ldsm4(uint32_t& r0, uint32_t& r1,
                                      uint32_t& r2, uint32_t& r3, uint32_t a) {
    asm volatile("ldmatrix.sync.aligned.m8n8.x4.shared.b16 {%0,%1,%2,%3}, [%4];"
                 : "=r"(r0), "=r"(r1), "=r"(r2), "=r"(r3) : "r"(a));
}

__device__ __forceinline__ void mma_bf16(float* c, const uint32_t* a, const uint32_t* b) {
    asm volatile(
        "mma.sync.aligned.m16n8k16.row.col.f32.bf16.bf16.f32 "
        "{%0,%1,%2,%3}, {%4,%5,%6,%7}, {%8,%9}, {%0,%1,%2,%3};"
        : "+f"(c[0]), "+f"(c[1]), "+f"(c[2]), "+f"(c[3])
        : "r"(a[0]), "r"(a[1]), "r"(a[2]), "r"(a[3]), "r"(b[0]), "r"(b[1]));
}

// fp32 pair -> bf16 hi + bf16 lo (residual) packed as b32
__device__ __forceinline__ void split2(float x, float y, uint32_t& hi, uint32_t& lo) {
    __nv_bfloat162 h = __floats2bfloat162_rn(x, y);
    float rx = x - __bfloat162float(__low2bfloat16(h));
    float ry = y - __bfloat162float(__high2bfloat16(h));
    __nv_bfloat162 l = __floats2bfloat162_rn(rx, ry);
    hi = *(uint32_t*)&h;
    lo = *(uint32_t*)&l;
}

// ---------------------------------------------------------------------------
// LayerNorm: one warp per token row of 128 floats
// ---------------------------------------------------------------------------
__global__ void ln_kernel(const float* __restrict__ X,
                          const float* __restrict__ s,
                          const float* __restrict__ b,
                          float* __restrict__ O, int rows)
{
    int gw   = (blockIdx.x * blockDim.x + threadIdx.x) >> 5;
    int lane = threadIdx.x & 31;
    if (gw >= rows) return;
    float4 v = ((const float4*)(X + (size_t)gw * 128))[lane];
    float sum = v.x + v.y + v.z + v.w;
    #pragma unroll
    for (int o = 16; o; o >>= 1) sum += __shfl_xor_sync(0xffffffffu, sum, o);
    float mean = sum * (1.0f / 128.0f);
    float dx = (v.x - mean) * (v.x - mean) + (v.y - mean) * (v.y - mean)
             + (v.z - mean) * (v.z - mean) + (v.w - mean) * (v.w - mean);
    #pragma unroll
    for (int o = 16; o; o >>= 1) dx += __shfl_xor_sync(0xffffffffu, dx, o);
    float rstd = rsqrtf(dx * (1.0f / 128.0f) + EPS);
    float4 sv = ((const float4*)s)[lane];
    float4 bv = ((const float4*)b)[lane];
    float4 o4;
    o4.x = (v.x - mean) * rstd * sv.x + bv.x;
    o4.y = (v.y - mean) * rstd * sv.y + bv.y;
    o4.z = (v.z - mean) * rstd * sv.z + bv.z;
    o4.w = (v.w - mean) * rstd * sv.w + bv.w;
    ((float4*)(O + (size_t)gw * 128))[lane] = o4;
}

// ---------------------------------------------------------------------------
// Split-bf16 tensor-core GEMM: C[M,N] = A[M,K] @ B[K,N] + bias (+res) (gelu)
// CTA tile 128x64, BK=32, 256 threads (8 warps, 4x2, warp tile 32x32).
// A,B split hi/lo bf16; D = Ahi*Bhi + Ahi*Blo + Alo*Bhi  (fp32 accum).
// Register prefetch of next chunk overlaps global latency with MMA.
// EPI: 0 = bias, 1 = bias + residual, 2 = bias + exact GELU
// ---------------------------------------------------------------------------
constexpr int AST = 40;   // smem row stride (bf16 elems): 80B, 16B-aligned, conflict-free
constexpr int BST = 40;

template <int EPI>
__global__ __launch_bounds__(256, 2)
void gemm_mma(const float* __restrict__ A, const float* __restrict__ Bw,
              const float* __restrict__ bias, const float* __restrict__ Res,
              float* __restrict__ C, int Nc, int K, int Mreal)
{
    __shared__ __nv_bfloat16 sAhi[128 * AST], sAlo[128 * AST];
    __shared__ __nv_bfloat16 sBhi[64 * BST],  sBlo[64 * BST];

    const int tid  = threadIdx.x;
    const int lane = tid & 31;
    const int wid  = tid >> 5;
    const int wm   = wid & 3;          // warp row (4 x 32 = 128 M)
    const int wn   = wid >> 2;         // warp col (2 x 32 = 64 N)
    const int m0   = blockIdx.y * 128;
    const int gn0  = blockIdx.x * 64;

    float acc[2][4][4] = {};           // [mtile][ntile][4]

    float4 pa[4];                      // prefetch: A 128x32 -> 1024 float4 / 256 thr
    float2 pb[4];                      // prefetch: B 16 kpairs x 64 n -> 1024 / 256 thr

    const int nch = K / 32;

    // --- global load of chunk c into registers
    auto loadg = [&](int c) {
        const int k0 = c * 32;
        #pragma unroll
        for (int i = 0; i < 4; i++) {
            int u = i * 256 + tid, row = u >> 3, c4 = u & 7;
            pa[i] = *(const float4*)(A + (size_t)(m0 + row) * K + k0 + c4 * 4);
        }
        #pragma unroll
        for (int i = 0; i < 4; i++) {
            int u = i * 256 + tid, kp = u >> 6, n = u & 63;
            pb[i].x = Bw[(size_t)(k0 + 2 * kp)     * Nc + gn0 + n];
            pb[i].y = Bw[(size_t)(k0 + 2 * kp + 1) * Nc + gn0 + n];
        }
    };

    // --- convert + store prefetched regs into smem
    auto store_s = [&]() {
        #pragma unroll
        for (int i = 0; i < 4; i++) {
            int u = i * 256 + tid, row = u >> 3, c4 = u & 7;
            uint32_t h0, l0, h1, l1;
            split2(pa[i].x, pa[i].y, h0, l0);
            split2(pa[i].z, pa[i].w, h1, l1);
            uint2 hv; hv.x = h0; hv.y = h1;
            uint2 lv; lv.x = l0; lv.y = l1;
            *(uint2*)(sAhi + row * AST + c4 * 4) = hv;
            *(uint2*)(sAlo + row * AST + c4 * 4) = lv;
        }
        #pragma unroll
        for (int i = 0; i < 4; i++) {
            int u = i * 256 + tid, kp = u >> 6, n = u & 63;
            uint32_t h, l;
            split2(pb[i].x, pb[i].y, h, l);
            *(uint32_t*)(sBhi + n * BST + 2 * kp) = h;
            *(uint32_t*)(sBlo + n * BST + 2 * kp) = l;
        }
    };

    const uint32_t aHi = s2u(sAhi), aLo = s2u(sAlo);
    const uint32_t bHi = s2u(sBhi), bLo = s2u(sBlo);

    // ldmatrix lane address components
    const int asub = lane >> 3;
    const int arow = (lane & 7) + (asub & 1) * 8;     // row within 16
    const int acol = (asub >> 1) * 8;                 // k: 0 or 8
    const int bnof = (lane & 7) + ((lane >> 3) >> 1) * 8;  // n within 16
    const int bkof = ((lane >> 3) & 1) * 8;                // k: 0 or 8

    loadg(0);
    for (int c = 0; c < nch; c++) {
        if (c) __syncthreads();        // mma of previous chunk done with smem
        store_s();
        __syncthreads();
        if (c + 1 < nch) loadg(c + 1); // overlap next-chunk loads with MMA

        #pragma unroll
        for (int ks = 0; ks < 2; ks++) {
            uint32_t ah[2][4], al[2][4], bh[4][2], bl[4][2];
            #pragma unroll
            for (int mt = 0; mt < 2; mt++) {
                uint32_t off = (uint32_t)((wm * 32 + mt * 16 + arow) * AST + ks * 16 + acol) * 2;
                ldsm4(ah[mt][0], ah[mt][1], ah[mt][2], ah[mt][3], aHi + off);
                ldsm4(al[mt][0], al[mt][1], al[mt][2], al[mt][3], aLo + off);
            }
            #pragma unroll
            for (int np = 0; np < 2; np++) {
                uint32_t off = (uint32_t)((wn * 32 + np * 16 + bnof) * BST + ks * 16 + bkof) * 2;
                ldsm4(bh[2*np][0], bh[2*np][1], bh[2*np+1][0], bh[2*np+1][1], bHi + off);
                ldsm4(bl[2*np][0], bl[2*np][1], bl[2*np+1][0], bl[2*np+1][1], bLo + off);
            }
            #pragma unroll
            for (int mt = 0; mt < 2; mt++)
                #pragma unroll
                for (int nt = 0; nt < 4; nt++) {
                    mma_bf16(acc[mt][nt], ah[mt], bh[nt]);
                    mma_bf16(acc[mt][nt], ah[mt], bl[nt]);
                    mma_bf16(acc[mt][nt], al[mt], bh[nt]);
                }
        }
    }

    // --- epilogue (fragment layout: c0,c1 = (r, 2c),(r,2c+1); c2,c3 = r+8)
    const int r0 = m0 + wm * 32 + (lane >> 2);
    const int c0 = gn0 + wn * 32 + (lane & 3) * 2;
    #pragma unroll
    for (int mt = 0; mt < 2; mt++) {
        #pragma unroll
        for (int half = 0; half < 2; half++) {
            int r = r0 + mt * 16 + half * 8;
            if (r < Mreal) {
                #pragma unroll
                for (int nt = 0; nt < 4; nt++) {
                    int cc = c0 + nt * 8;
                    float v0 = acc[mt][nt][half * 2 + 0] + bias[cc];
                    float v1 = acc[mt][nt][half * 2 + 1] + bias[cc + 1];
                    if (EPI == 1) {
                        float2 rv = *(const float2*)(Res + (size_t)r * Nc + cc);
                        v0 += rv.x; v1 += rv.y;
                    }
                    if (EPI == 2) {
                        v0 = 0.5f * v0 * (1.0f + erff(v0 * 0.70710678118654752f));
                        v1 = 0.5f * v1 * (1.0f + erff(v1 * 0.70710678118654752f));
                    }
                    float2 o; o.x = v0; o.y = v1;
                    *(float2*)(C + (size_t)r * Nc + cc) = o;
                }
            }
        }
    }
}

// ---------------------------------------------------------------------------
// Temporal attention: block per (b,n,head), L=48, HD=16 — float4 smem reads
// ---------------------------------------------------------------------------
__global__ __launch_bounds__(64)
void attn_temporal(const float* __restrict__ qkv, float* __restrict__ att)
{
    int h  = blockIdx.x & 7;
    int bn = blockIdx.x >> 3;
    __shared__ float q[48][16], k[48][16], v[48][16];
    __shared__ float sc[48][48];
    int tid = threadIdx.x;

    size_t base = (size_t)bn * 48 * 384 + h * 16;
    for (int i = tid; i < 48 * 4; i += 64) {
        int row = i >> 2, seg = i & 3;
        const float* p = qkv + base + (size_t)row * 384;
        ((float4*)q[row])[seg] = ((const float4*)(p))[seg];
        ((float4*)k[row])[seg] = ((const float4*)(p + 128))[seg];
        ((float4*)v[row])[seg] = ((const float4*)(p + 256))[seg];
    }
    __syncthreads();

    for (int i = tid; i < 48 * 48; i += 64) {
        int qi = i / 48, ki = i % 48;
        const float4* q4 = (const float4*)q[qi];
        const float4* k4 = (const float4*)k[ki];
        float4 a0 = q4[0], a1 = q4[1], a2 = q4[2], a3 = q4[3];
        float4 b0 = k4[0], b1 = k4[1], b2 = k4[2], b3 = k4[3];
        float s = a0.x*b0.x + a0.y*b0.y + a0.z*b0.z + a0.w*b0.w
                + a1.x*b1.x + a1.y*b1.y + a1.z*b1.z + a1.w*b1.w
                + a2.x*b2.x + a2.y*b2.y + a2.z*b2.z + a2.w*b2.w
                + a3.x*b3.x + a3.y*b3.y + a3.z*b3.z + a3.w*b3.w;
        sc[qi][ki] = s * SCALE;
    }
    __syncthreads();

    if (tid < 48) {
        float mx = -3.4e38f;
        for (int j = 0; j < 48; j++) mx = fmaxf(mx, sc[tid][j]);
        float l = 0.f;
        for (int j = 0; j < 48; j++) {
            float p = __expf(sc[tid][j] - mx);
            sc[tid][j] = p; l += p;
        }
        float inv = 1.0f / l;
        for (int j = 0; j < 48; j++) sc[tid][j] *= inv;
    }
    __syncthreads();

    for (int i = tid; i < 48 * 4; i += 64) {       // (qi, 4-col segment)
        int qi = i >> 2, seg = i & 3;
        float4 o = make_float4(0.f, 0.f, 0.f, 0.f);
        for (int kk = 0; kk < 48; kk++) {
            float w = sc[qi][kk];
            float4 vv = ((const float4*)v[kk])[seg];
            o.x = fmaf(w, vv.x, o.x);
            o.y = fmaf(w, vv.y, o.y);
            o.z = fmaf(w, vv.z, o.z);
            o.w = fmaf(w, vv.w, o.w);
        }
        ((float4*)(att + (size_t)(bn * 48 + qi) * 128 + h * 16))[seg] = o;
    }
}

// ---------------------------------------------------------------------------
// Spatial attention (flash-style): block per (b,t,head), L=325 over n.
// float4 smem reads; mask read as int32.
// ---------------------------------------------------------------------------
constexpr int KT = 32;

__global__ __launch_bounds__(352)
void attn_spatial(const float* __restrict__ qkv, const int* __restrict__ mask,
                  float* __restrict__ att)
{
    int h  = blockIdx.x & 7;
    int bt = blockIdx.x >> 3;
    int t  = bt % Tt, b = bt / Tt;
    int tid = threadIdx.x;
    int nq  = tid;
    bool active = nq < Nn;

    __shared__ float ks[KT][16], vs[KT][16];
    __shared__ int   msk[KT];

    float4 qr[4];
    float4 acc[4];
    #pragma unroll
    for (int i = 0; i < 4; i++) acc[i] = make_float4(0.f, 0.f, 0.f, 0.f);
    float m = -3.4e38f, l = 0.f;

    if (active) {
        const float* p = qkv + ((size_t)(b * Nn + nq) * Tt + t) * 384 + h * 16;
        #pragma unroll
        for (int i = 0; i < 4; i++) qr[i] = ((const float4*)p)[i];
    }

    for (int kt = 0; kt < Nn; kt += KT) {
        int nk = min(KT, Nn - kt);
        __syncthreads();
        if (tid < 128) {
            int r = tid >> 2, seg = tid & 3;
            if (r < nk) {
                const float* p = qkv + ((size_t)(b * Nn + kt + r) * Tt + t) * 384 + 128 + h * 16;
                ((float4*)ks[r])[seg] = ((const float4*)p)[seg];
            }
        } else if (tid < 256) {
            int r = (tid - 128) >> 2, seg = tid & 3;
            if (r < nk) {
                const float* p = qkv + ((size_t)(b * Nn + kt + r) * Tt + t) * 384 + 256 + h * 16;
                ((float4*)vs[r])[seg] = ((const float4*)p)[seg];
            }
        } else if (tid < 256 + KT) {
            int j = tid - 256;
            msk[j] = (kt + j < Nn) ? (mask[b * Nn + kt + j] != 0 ? 1 : 0) : 0;
        }
        __syncthreads();

        if (active) {
            float sarr[KT];
            #pragma unroll
            for (int j = 0; j < KT; j++) {
                const float4* k4 = (const float4*)ks[j];
                float4 b0 = k4[0], b1 = k4[1], b2 = k4[2], b3 = k4[3];
                float d = qr[0].x*b0.x + qr[0].y*b0.y + qr[0].z*b0.z + qr[0].w*b0.w
                        + qr[1].x*b1.x + qr[1].y*b1.y + qr[1].z*b1.z + qr[1].w*b1.w
                        + qr[2].x*b2.x + qr[2].y*b2.y + qr[2].z*b2.z + qr[2].w*b2.w
                        + qr[3].x*b3.x + qr[3].y*b3.y + qr[3].z*b3.z + qr[3].w*b3.w;
                sarr[j] = msk[j] ? d * SCALE : -3.4e38f;
            }
            float tm = -3.4e38f;
            #pragma unroll
            for (int j = 0; j < KT; j++) tm = fmaxf(tm, sarr[j]);
            float mnew = fmaxf(m, tm);
            float corr = __expf(m - mnew);
            l *= corr;
            #pragma unroll
            for (int i = 0; i < 4; i++) {
                acc[i].x *= corr; acc[i].y *= corr; acc[i].z *= corr; acc[i].w *= corr;
            }
            #pragma unroll
            for (int j = 0; j < KT; j++) {
                float p = (sarr[j] > -3.0e38f) ? __expf(sarr[j] - mnew) : 0.f;
                l += p;
                const float4* v4 = (const float4*)vs[j];
                #pragma unroll
                for (int i = 0; i < 4; i++) {
                    float4 vv = v4[i];
                    acc[i].x = fmaf(p, vv.x, acc[i].x);
                    acc[i].y = fmaf(p, vv.y, acc[i].y);
                    acc[i].z = fmaf(p, vv.z, acc[i].z);
                    acc[i].w = fmaf(p, vv.w, acc[i].w);
                }
            }
            m = mnew;
        }
    }

    if (active) {
        float inv = 1.0f / l;
        float* o = att + ((size_t)(b * Nn + nq) * Tt + t) * 128 + h * 16;
        #pragma unroll
        for (int i = 0; i < 4; i++) {
            float4 ov;
            ov.x = acc[i].x * inv; ov.y = acc[i].y * inv;
            ov.z = acc[i].z * inv; ov.w = acc[i].w * inv;
            ((float4*)o)[i] = ov;
        }
    }
}

// ---------------------------------------------------------------------------
// Orchestration
// ---------------------------------------------------------------------------
extern "C" void kernel_launch(void* const* d_in, const int* in_sizes, int n_in,
                              void* d_out, int out_size)
{
    const float* x       = (const float*)d_in[0];
    const int*   mask    = (const int*)  d_in[1];
    const float* ln1_s   = (const float*)d_in[2];
    const float* ln1_b   = (const float*)d_in[3];
    const float* tqkv_w  = (const float*)d_in[4];
    const float* tqkv_b  = (const float*)d_in[5];
    const float* tproj_w = (const float*)d_in[6];
    const float* tproj_b = (const float*)d_in[7];
    const float* ln2_s   = (const float*)d_in[8];
    const float* ln2_b   = (const float*)d_in[9];
    const float* sqkv_w  = (const float*)d_in[10];
    const float* sqkv_b  = (const float*)d_in[11];
    const float* sproj_w = (const float*)d_in[12];
    const float* sproj_b = (const float*)d_in[13];
    const float* ln3_s   = (const float*)d_in[14];
    const float* ln3_b   = (const float*)d_in[15];
    const float* fw1     = (const float*)d_in[16];
    const float* fb1     = (const float*)d_in[17];
    const float* fw2     = (const float*)d_in[18];
    const float* fb2     = (const float*)d_in[19];
    float* out = (float*)d_out;

    float *h, *qkv, *att, *x1, *x2, *ffh;
    cudaGetSymbolAddress((void**)&h,   g_h);
    cudaGetSymbolAddress((void**)&qkv, g_qkv);
    cudaGetSymbolAddress((void**)&att, g_att);
    cudaGetSymbolAddress((void**)&x1,  g_x1);
    cudaGetSymbolAddress((void**)&x2,  g_x2);
    cudaGetSymbolAddress((void**)&ffh, g_ffh);

    const int ln_grid = (M + 7) / 8;           // 8 warps (256 thr) per block
    dim3 g_qkv_grid(384 / 64, MT);
    dim3 g_d_grid  (128 / 64, MT);
    dim3 g_ffn1    (512 / 64, MT);

    // ---- temporal branch ----
    ln_kernel<<<ln_grid, 256>>>(x, ln1_s, ln1_b, h, M);
    gemm_mma<0><<<g_qkv_grid, 256>>>(h, tqkv_w, tqkv_b, nullptr, qkv, 384, 128, M);
    attn_temporal<<<Bb * Nn * Hh, 64>>>(qkv, att);
    gemm_mma<1><<<g_d_grid, 256>>>(att, tproj_w, tproj_b, x, x1, 128, 128, M);

    // ---- spatial branch ----
    ln_kernel<<<ln_grid, 256>>>(x1, ln2_s, ln2_b, h, M);
    gemm_mma<0><<<g_qkv_grid, 256>>>(h, sqkv_w, sqkv_b, nullptr, qkv, 384, 128, M);
    attn_spatial<<<Bb * Tt * Hh, 352>>>(qkv, mask, att);
    gemm_mma<1><<<g_d_grid, 256>>>(att, sproj_w, sproj_b, x1, x2, 128, 128, M);

    // ---- FFN ----
    ln_kernel<<<ln_grid, 256>>>(x2, ln3_s, ln3_b, h, M);
    gemm_mma<2><<<g_ffn1, 256>>>(h, fw1, fb1, nullptr, ffh, 512, 128, M);
    gemm_mma<1><<<g_d_grid, 256>>>(ffh, fw2, fb2, x2, out, 128, 512, M);
}